// round 3
// baseline (speedup 1.0000x reference)
#include <cuda_runtime.h>
#include <cuda_bf16.h>
#include <math_constants.h>

#define N_TOKENS   8192
#define QUANT_DIM  8192
#define OUTPUT_DIM 1024

#define T_BX (QUANT_DIM / 32)    // 256 column-tiles
#define T_BY (OUTPUT_DIM / 32)   // 32 output-tiles

// Scratch (__device__ globals: the sanctioned allocation-free path)
__device__ int g_idx[N_TOKENS];
__device__ int g_offs[QUANT_DIM + 1];   // CSR column starts
__device__ int g_tokens[N_TOKENS];      // tokens sorted by argmax column

// ---------------------------------------------------------------------------
// Kernel 1: per-row argmax of x [N_TOKENS, QUANT_DIM]. One block per row.
// First-index tie-break (jnp.argmax semantics).
// ---------------------------------------------------------------------------
__global__ __launch_bounds__(256) void argmax_rows_kernel(
    const float* __restrict__ x, int* __restrict__ idx_out)
{
    const int row = blockIdx.x;
    const float4* __restrict__ xr =
        reinterpret_cast<const float4*>(x + (size_t)row * QUANT_DIM);

    float best = -CUDART_INF_F;
    int   bidx = 0;

    #pragma unroll
    for (int it = 0; it < 8; ++it) {
        const int i = threadIdx.x + it * 256;
        const float4 v = __ldcs(&xr[i]);           // streaming read
        const float vm = fmaxf(fmaxf(v.x, v.y), fmaxf(v.z, v.w));
        if (vm > best) {                            // rare after warmup
            best = vm;
            const int base = i * 4;
            bidx = (v.x == vm) ? base
                 : (v.y == vm) ? base + 1
                 : (v.z == vm) ? base + 2
                 :               base + 3;          // first-equal = first index
        }
    }

    #pragma unroll
    for (int off = 16; off > 0; off >>= 1) {
        float ov = __shfl_down_sync(0xFFFFFFFFu, best, off);
        int   oi = __shfl_down_sync(0xFFFFFFFFu, bidx, off);
        if (ov > best || (ov == best && oi < bidx)) { best = ov; bidx = oi; }
    }

    __shared__ float s_val[8];
    __shared__ int   s_idx[8];
    const int lane = threadIdx.x & 31;
    const int warp = threadIdx.x >> 5;
    if (lane == 0) { s_val[warp] = best; s_idx[warp] = bidx; }
    __syncthreads();

    if (warp == 0) {
        best = (lane < 8) ? s_val[lane] : -CUDART_INF_F;
        bidx = (lane < 8) ? s_idx[lane] : 0x7FFFFFFF;
        #pragma unroll
        for (int off = 4; off > 0; off >>= 1) {
            float ov = __shfl_down_sync(0xFFFFFFFFu, best, off);
            int   oi = __shfl_down_sync(0xFFFFFFFFu, bidx, off);
            if (ov > best || (ov == best && oi < bidx)) { best = ov; bidx = oi; }
        }
        if (lane == 0) idx_out[row] = bidx;
    }
}

// ---------------------------------------------------------------------------
// Kernel 2: build CSR (idx -> token list). Single block, 1024 threads.
// smem histogram -> in-place exclusive prefix -> scatter. Order within a
// column is arbitrary (atomics) but the final output is order-invariant.
// ---------------------------------------------------------------------------
__global__ __launch_bounds__(1024) void build_index_kernel(
    const int* __restrict__ idx, int* __restrict__ offs_g,
    int* __restrict__ tokens_g)
{
    __shared__ int s[QUANT_DIM];     // 32 KB: counts -> offsets -> cursors
    __shared__ int s_warp[32];

    const int tid  = threadIdx.x;
    const int lane = tid & 31;
    const int wid  = tid >> 5;
    const int base = tid * 8;        // each thread owns 8 contiguous slots

    // 1) zero histogram
    #pragma unroll
    for (int j = 0; j < 8; ++j) s[base + j] = 0;
    __syncthreads();

    // 2) histogram of idx
    #pragma unroll
    for (int j = 0; j < 8; ++j) atomicAdd(&s[idx[base + j] & (QUANT_DIM - 1)], 1);
    __syncthreads();

    // 3) exclusive prefix sum, in place (each thread reads/writes only its 8)
    int c[8];
    int chunk = 0;
    #pragma unroll
    for (int j = 0; j < 8; ++j) { c[j] = s[base + j]; chunk += c[j]; }

    int v = chunk;
    #pragma unroll
    for (int off = 1; off < 32; off <<= 1) {
        int n = __shfl_up_sync(0xFFFFFFFFu, v, off);
        if (lane >= off) v += n;
    }
    if (lane == 31) s_warp[wid] = v;
    __syncthreads();
    if (wid == 0) {
        int w = s_warp[lane];
        #pragma unroll
        for (int off = 1; off < 32; off <<= 1) {
            int n = __shfl_up_sync(0xFFFFFFFFu, w, off);
            if (lane >= off) w += n;
        }
        s_warp[lane] = w;
    }
    __syncthreads();

    int run = (v - chunk) + (wid ? s_warp[wid - 1] : 0);   // exclusive base
    #pragma unroll
    for (int j = 0; j < 8; ++j) {
        s[base + j] = run;
        offs_g[base + j] = run;
        run += c[j];
    }
    if (tid == 0) offs_g[QUANT_DIM] = N_TOKENS;
    __syncthreads();

    // 4) scatter tokens using smem offsets as cursors
    #pragma unroll
    for (int j = 0; j < 8; ++j) {
        const int t = base + j;
        const int p = atomicAdd(&s[idx[t] & (QUANT_DIM - 1)], 1);
        tokens_g[p] = t;
    }
}

// ---------------------------------------------------------------------------
// Kernel 3: tile gather. Block (bx, by) loads W tile [32 out-rows x 32 cols]
// coalesced into padded smem; for each token whose argmax column lies in this
// tile's 32 columns, one warp writes 32 contiguous floats of out[token].
// W is read exactly once; out written exactly once. No Wt round-trip.
// ---------------------------------------------------------------------------
__global__ __launch_bounds__(256) void tile_gather_kernel(
    const float* __restrict__ W, const int* __restrict__ idx,
    const int* __restrict__ offs, const int* __restrict__ tokens,
    float* __restrict__ out)
{
    __shared__ float tile[32 * 33];
    __shared__ int   s_base, s_npairs;

    const int bx = blockIdx.x;       // column tile (quant dim)
    const int by = blockIdx.y;       // output tile
    const int tx = threadIdx.x & 31;
    const int ty = threadIdx.x >> 5; // 0..7 (also warp id)

    if (threadIdx.x == 0) {
        const int b = offs[bx * 32];
        s_base   = b;
        s_npairs = offs[bx * 32 + 32] - b;
    }

    // load W tile: row = output dim, col = quant dim (coalesced 128B/warp)
    #pragma unroll
    for (int j = 0; j < 32; j += 8)
        tile[(ty + j) * 33 + tx] =
            W[(size_t)(by * 32 + ty + j) * QUANT_DIM + bx * 32 + tx];

    __syncthreads();

    const int base   = s_base;
    const int npairs = s_npairs;

    // one warp per (column, token) pair; lane = output element within chunk
    for (int p = ty; p < npairs; p += 8) {
        const int token   = tokens[base + p];            // broadcast load
        const int c_local = idx[token] - bx * 32;        // in [0, 32)
        const float val   = tile[tx * 33 + c_local];     // conflict-free col read
        __stcs(&out[(size_t)token * OUTPUT_DIM + by * 32 + tx], val);
    }
}

// ---------------------------------------------------------------------------
extern "C" void kernel_launch(void* const* d_in, const int* in_sizes, int n_in,
                              void* d_out, int out_size)
{
    const float* x = (const float*)d_in[0];   // [8192, 8192] fp32
    const float* W = (const float*)d_in[1];   // [1024, 8192] fp32
    float* out = (float*)d_out;               // [8192, 1024] fp32

    int *idx_dev, *offs_dev, *tok_dev;
    cudaGetSymbolAddress((void**)&idx_dev,  g_idx);
    cudaGetSymbolAddress((void**)&offs_dev, g_offs);
    cudaGetSymbolAddress((void**)&tok_dev,  g_tokens);

    argmax_rows_kernel<<<N_TOKENS, 256>>>(x, idx_dev);
    build_index_kernel<<<1, 1024>>>(idx_dev, offs_dev, tok_dev);
    tile_gather_kernel<<<dim3(T_BX, T_BY), 256>>>(W, idx_dev, offs_dev,
                                                  tok_dev, out);
}

// round 4
// speedup vs baseline: 1.1591x; 1.1591x over previous
#include <cuda_runtime.h>
#include <cuda_bf16.h>
#include <math_constants.h>

#define N_TOKENS   8192
#define QUANT_DIM  8192
#define OUTPUT_DIM 1024

// ---------------------------------------------------------------------------
// Single fused kernel: one block per token row.
//  Phase 1: argmax over x[row][0..8191]  (first-index tie-break, jnp semantics)
//  Phase 2: out[row][c] = W[c][idx]  for c = 0..1023
//           - W loads: 32 distinct 32B sectors per warp; W is L2-resident
//             (32 MB) and each sector is reused by ~8 tokens on average.
//           - out stores: fully coalesced, streaming.
//  x is read with .cs (evict-first) so it doesn't evict W from L2.
// ---------------------------------------------------------------------------
__global__ __launch_bounds__(256) void argmax_gather_kernel(
    const float* __restrict__ x, const float* __restrict__ W,
    float* __restrict__ out)
{
    const int row = blockIdx.x;
    const float4* __restrict__ xr =
        reinterpret_cast<const float4*>(x + (size_t)row * QUANT_DIM);

    float best = -CUDART_INF_F;
    int   bidx = 0;

    // ---- Phase 1: argmax (8192 floats = 2048 float4, 8 iters/thread) ----
    #pragma unroll
    for (int it = 0; it < 8; ++it) {
        const int i = threadIdx.x + it * 256;
        const float4 v = __ldcs(&xr[i]);          // streaming: keep W in L2
        const float vm = fmaxf(fmaxf(v.x, v.y), fmaxf(v.z, v.w));
        if (vm > best) {                           // rare after warmup
            best = vm;
            const int base = i * 4;
            bidx = (v.x == vm) ? base
                 : (v.y == vm) ? base + 1
                 : (v.z == vm) ? base + 2
                 :               base + 3;         // first-equal = first index
        }
    }

    // warp reduce: value desc, index asc on exact tie
    #pragma unroll
    for (int off = 16; off > 0; off >>= 1) {
        float ov = __shfl_down_sync(0xFFFFFFFFu, best, off);
        int   oi = __shfl_down_sync(0xFFFFFFFFu, bidx, off);
        if (ov > best || (ov == best && oi < bidx)) { best = ov; bidx = oi; }
    }

    __shared__ float s_val[8];
    __shared__ int   s_idx[8];
    __shared__ int   s_result;
    const int lane = threadIdx.x & 31;
    const int warp = threadIdx.x >> 5;
    if (lane == 0) { s_val[warp] = best; s_idx[warp] = bidx; }
    __syncthreads();

    if (warp == 0) {
        best = (lane < 8) ? s_val[lane] : -CUDART_INF_F;
        bidx = (lane < 8) ? s_idx[lane] : 0x7FFFFFFF;
        #pragma unroll
        for (int off = 4; off > 0; off >>= 1) {
            float ov = __shfl_down_sync(0xFFFFFFFFu, best, off);
            int   oi = __shfl_down_sync(0xFFFFFFFFu, bidx, off);
            if (ov > best || (ov == best && oi < bidx)) { best = ov; bidx = oi; }
        }
        if (lane == 0) s_result = bidx;
    }
    __syncthreads();

    // ---- Phase 2: gather column idx of W into out[row] ----
    const int idx = s_result;                      // uniform per block
    const float* __restrict__ Wcol = W + idx;      // column base
    float* __restrict__ dst = out + (size_t)row * OUTPUT_DIM;

    // 4 independent loads per thread (MLP=4 hides L2 latency);
    // stores coalesced: consecutive threads -> consecutive floats.
    float v0 = __ldg(&Wcol[(size_t)(threadIdx.x      ) * QUANT_DIM]);
    float v1 = __ldg(&Wcol[(size_t)(threadIdx.x + 256) * QUANT_DIM]);
    float v2 = __ldg(&Wcol[(size_t)(threadIdx.x + 512) * QUANT_DIM]);
    float v3 = __ldg(&Wcol[(size_t)(threadIdx.x + 768) * QUANT_DIM]);
    __stcs(&dst[threadIdx.x      ], v0);
    __stcs(&dst[threadIdx.x + 256], v1);
    __stcs(&dst[threadIdx.x + 512], v2);
    __stcs(&dst[threadIdx.x + 768], v3);
}

// ---------------------------------------------------------------------------
extern "C" void kernel_launch(void* const* d_in, const int* in_sizes, int n_in,
                              void* d_out, int out_size)
{
    const float* x = (const float*)d_in[0];   // [8192, 8192] fp32
    const float* W = (const float*)d_in[1];   // [1024, 8192] fp32
    float* out = (float*)d_out;               // [8192, 1024] fp32

    argmax_gather_kernel<<<N_TOKENS, 256>>>(x, W, out);
}